// round 15
// baseline (speedup 1.0000x reference)
#include <cuda_runtime.h>
#include <cuda_fp16.h>
#include <cstdint>

// Problem sizes (fixed by the dataset)
#define B_  32
#define S_  512
#define H_  768
#define MS_ 128
#define SL_ 8
#define M_  (B_ * S_)        // 16384 rows of X
#define NT_ 6                // partial-logit slices (one per n-block)

#define NEG_INF -1e30f

// Scratch (device globals: no allocation allowed)
__device__ float g_part[NT_ * M_];                 // partial logits per n-slice
__device__ float g_attn[M_];                       // softmax weights a[b,s]
__device__ float g_sacc[B_ * 3 * 16 * 256];        // weighted-sum partials
__device__ __half Xh[M_ * H_];                     // natural-layout fp16 X
// Fragment-major tiles: per (tile, chunk32) 2048 words (8KB), fp16.
__device__ uint4 Xfrag[M_ * H_ / 8];
__device__ uint4 Wfrag[H_ * H_ / 8];

// ---------------------------------------------------------------------------
// helpers
// ---------------------------------------------------------------------------
__device__ __forceinline__ uint32_t smem_u32(const void* p) {
    uint32_t a;
    asm("{ .reg .u64 t; cvta.to.shared.u64 t, %1; cvt.u32.u64 %0, t; }"
        : "=r"(a) : "l"(p));
    return a;
}

#define CP_ASYNC16(dst, src) \
    asm volatile("cp.async.cg.shared.global [%0], [%1], 16;" :: "r"(dst), "l"(src))
#define CP_COMMIT() asm volatile("cp.async.commit_group;" ::: "memory")
#define CP_WAIT0()  asm volatile("cp.async.wait_group 0;" ::: "memory")
#define CP_WAIT1()  asm volatile("cp.async.wait_group 1;" ::: "memory")

__device__ __forceinline__ void mma_f16(float* d, const uint32_t* a, const uint32_t* b) {
    asm volatile("mma.sync.aligned.m16n8k16.row.col.f32.f16.f16.f32 "
        "{%0,%1,%2,%3}, {%4,%5,%6,%7}, {%8,%9}, {%0,%1,%2,%3};"
        : "+f"(d[0]), "+f"(d[1]), "+f"(d[2]), "+f"(d[3])
        : "r"(a[0]), "r"(a[1]), "r"(a[2]), "r"(a[3]), "r"(b[0]), "r"(b[1]));
}

// fast tanh: tanh(x) = 1 - 2/(exp(2x)+1). 2 MUFU, abs err ~1e-6.
__device__ __forceinline__ float tanh_fast(float x) {
    float e = __expf(2.0f * x);
    return 1.0f - __fdividef(2.0f, e + 1.0f);
}

// pack two fp32 -> fp16x2 word
__device__ __forceinline__ uint32_t pack_h2(float x0, float x1) {
    __half h0 = __float2half_rn(x0);
    __half h1 = __float2half_rn(x1);
    return (uint32_t)__half_as_ushort(h0) | ((uint32_t)__half_as_ushort(h1) << 16);
}

// ---------------------------------------------------------------------------
// Fragment word layouts (word index within an 8KB chunk32 tile of 2048 words)
//   A tile: 128m x 32k.  W = ((mt*2+ks)*32 + lane)*4 + r
//   B tile: 128n x 32k, PAIRED: W = ((ntp*2+ks)*32 + lane)*4 + sub*2 + r
//     (ntp=nt>>1, sub=nt&1) — one LDS.128 feeds two adjacent n-tiles.
// ---------------------------------------------------------------------------

// Kernel 0: prepass. 1D grid:
//   bid < 24*128 : X -> Xfrag (+ natural fp16 copy Xh)
//   else         : W -> Wfrag (paired-B layout)
#define XSPLIT_BLOCKS (24 * 128)
#define SPLIT_BLOCKS  (24 * 134)

__global__ __launch_bounds__(256) void prep_kernel(
    const float* __restrict__ X, const float* __restrict__ W) {

    __shared__ float sbuf[4224];
    int bid = blockIdx.x;
    int t = threadIdx.x;

    if (bid < XSPLIT_BLOCKS) {
        int c = bid % 24, mb = bid / 24;
        float (*sX)[33] = (float (*)[33])sbuf;   // [128][33]
#pragma unroll
        for (int i = 0; i < 16; i++) {
            int idx = t + i * 256;  // 0..4095
            int m = idx >> 5, k = idx & 31;
            float x = X[(size_t)(mb * 128 + m) * H_ + c * 32 + k];
            sX[m][k] = x;
            Xh[(size_t)(mb * 128 + m) * H_ + c * 32 + k] = __float2half_rn(x);
        }
        __syncthreads();

        uint32_t* oh = (uint32_t*)Xfrag + ((size_t)mb * 24 + c) * 2048;
#pragma unroll
        for (int p = 0; p < 8; p++) {
            int w = t + p * 256;    // 0..2047
            int r = w & 3, lane = (w >> 2) & 31, g = w >> 7;   // g = mt*2+ks
            int mt = g >> 1, ks = g & 1;
            int m  = mt * 16 + ((r & 1) << 3) + (lane >> 2);
            int kp = ks * 8 + ((r >> 1) << 2) + (lane & 3);
            oh[w] = pack_h2(sX[m][2 * kp], sX[m][2 * kp + 1]);
        }
    } else {
        int bid2 = bid - XSPLIT_BLOCKS;
        int c = bid2 % 24, nb = bid2 / 24;
        float (*sW)[129] = (float (*)[129])sbuf; // [32][129]
#pragma unroll
        for (int i = 0; i < 16; i++) {
            int idx = t + i * 256;  // 0..4095
            int k = idx >> 7, n = idx & 127;
            sW[k][n] = W[(size_t)(c * 32 + k) * H_ + nb * 128 + n];
        }
        __syncthreads();

        uint32_t* oh = (uint32_t*)Wfrag + ((size_t)nb * 24 + c) * 2048;
#pragma unroll
        for (int p = 0; p < 8; p++) {
            int w = t + p * 256;
            int r2 = w & 3, lane = (w >> 2) & 31, g = w >> 7;  // g = ntp*2+ks
            int sub = r2 >> 1, r = r2 & 1;
            int ntp = g >> 1, ks = g & 1;
            int nt = ntp * 2 + sub;
            int n  = nt * 8 + (lane >> 2);
            int kp = ks * 8 + (r << 2) + (lane & 3);
            oh[w] = pack_h2(sW[2 * kp][n], sW[2 * kp + 1][n]);
        }
    }
}

// ---------------------------------------------------------------------------
// Kernel 2: fp16 mma.sync GEMM + fused tanh/w_ctx epilogue, WITH trailing
//   gather_max blocks fused into the same launch (they fill the GEMM's
//   partially-idle last wave).
//   1D grid: bid < 768 -> GEMM tile (bx=bid%6 n-block, by=bid/6 m-tile)
//            bid >= 768 -> gather segment bm = bid - 768
// ---------------------------------------------------------------------------
#define SA_OFF 0
#define SB_OFF 16384
#define BUFSZ 32768
#define STAGES 3
#define SM_REQ (STAGES * BUFSZ)
#define GEMM_BLOCKS (6 * 128)

__global__ __launch_bounds__(256, 2) void gemm_mma_kernel(
    const float* __restrict__ b_attn, const float* __restrict__ w_ctx,
    const float* __restrict__ X, const int* __restrict__ segments,
    const int* __restrict__ seg_mask, const int* __restrict__ idx_mask,
    float* __restrict__ out) {

    extern __shared__ __align__(128) char smb[];

    if (blockIdx.x >= GEMM_BLOCKS) {
        // ---- gather_max path ----
        int bm = blockIdx.x - GEMM_BLOCKS;
        int b  = bm >> 7;
        int t  = threadIdx.x;
        int* sidx   = (int*)smb;
        int* svalid = (int*)smb + SL_;
        if (t < SL_) {
            sidx[t]   = segments[bm * SL_ + t];
            svalid[t] = idx_mask[bm * SL_ + t];
        }
        __syncthreads();
        if (t < 192) {
            const float4* Xb = (const float4*)(X + (size_t)b * S_ * H_);
            bool ok = seg_mask[bm] != 0;
            float4 r;
            if (!ok) {
                r = Xb[(size_t)(S_ - 2) * (H_ / 4) + t];
            } else {
                r = make_float4(NEG_INF, NEG_INF, NEG_INF, NEG_INF);
#pragma unroll
                for (int sl = 0; sl < SL_; sl++) {
                    if (svalid[sl]) {
                        float4 v = Xb[(size_t)sidx[sl] * (H_ / 4) + t];
                        r.x = fmaxf(r.x, v.x);
                        r.y = fmaxf(r.y, v.y);
                        r.z = fmaxf(r.z, v.z);
                        r.w = fmaxf(r.w, v.w);
                    }
                }
            }
            ((float4*)out)[(size_t)bm * (H_ / 4) + t] = r;
        }
        return;
    }

    // ---- GEMM path ----
    uint32_t sbu = smem_u32(smb);
    int bx = blockIdx.x % 6;
    int by = blockIdx.x / 6;

    int tid  = threadIdx.x;
    int wid  = tid >> 5, lane = tid & 31;
    int wm   = wid >> 2, wn = wid & 3;        // warp grid 2(m) x 4(n)
    int n0   = bx * 128;

    const char* gA = (const char*)Xfrag + (size_t)by * 24 * 8192;
    const char* gB = (const char*)Wfrag + (size_t)bx * 24 * 8192;

    float d[4][4][4];
#pragma unroll
    for (int i = 0; i < 4; i++)
#pragma unroll
        for (int j = 0; j < 4; j++)
#pragma unroll
            for (int r = 0; r < 4; r++) d[i][j][r] = 0.f;

    auto stage = [&](int c, uint32_t buf) {   // c in chunk64 units (0..11)
        size_t tb = (size_t)c * 16384;
#pragma unroll
        for (int p = 0; p < 4; p++) {
            uint32_t off = (uint32_t)(tid + p * 256) * 16;
            CP_ASYNC16(buf + SA_OFF + off, gA + tb + off);
            CP_ASYNC16(buf + SB_OFF + off, gB + tb + off);
        }
    };

    auto compute = [&](const char* buf) {
#pragma unroll
        for (int half = 0; half < 2; half++) {
            const char* Ab = buf + SA_OFF + half * 8192;
            const char* Bb = buf + SB_OFF + half * 8192;
#pragma unroll
            for (int ks = 0; ks < 2; ks++) {
                uint32_t a[4][4], b[4][2];
#pragma unroll
                for (int mt = 0; mt < 4; mt++) {
                    uint32_t aoff = (((wm * 4 + mt) * 2 + ks) * 32 + lane) * 16;
                    uint4 v = *(const uint4*)(Ab + aoff);
                    a[mt][0] = v.x; a[mt][1] = v.y; a[mt][2] = v.z; a[mt][3] = v.w;
                }
#pragma unroll
                for (int ntp = 0; ntp < 2; ntp++) {
                    uint32_t boff = (((wn * 2 + ntp) * 2 + ks) * 32 + lane) * 16;
                    uint4 v = *(const uint4*)(Bb + boff);
                    b[2 * ntp][0]     = v.x; b[2 * ntp][1]     = v.y;
                    b[2 * ntp + 1][0] = v.z; b[2 * ntp + 1][1] = v.w;
                }
#pragma unroll
                for (int mt = 0; mt < 4; mt++)
#pragma unroll
                    for (int nt = 0; nt < 4; nt++)
                        mma_f16(d[mt][nt], a[mt], b[nt]);
            }
        }
    };

    // ---- prologue: stages 0 and 1 in flight ----
    stage(0, sbu);
    CP_COMMIT();
    stage(1, sbu + BUFSZ);
    CP_COMMIT();

    // ---- mainloop: 12 chunk64s, 3-stage pipeline, compile-time stage idx ----
    for (int cb = 0; cb < 12; cb += 3) {
#pragma unroll
        for (int j = 0; j < 3; j++) {
            int c = cb + j;
            if (c == 11) CP_WAIT0(); else CP_WAIT1();
            __syncthreads();
            compute(smb + j * BUFSZ);
            if (c + 2 < 12) {
                stage(c + 2, sbu + ((j + 2) % 3) * BUFSZ);
                CP_COMMIT();
            }
        }
    }

    // ---- fused epilogue: tanh + dot(w_ctx), shfl + SMEM reduce -> 1 slice ----
    __syncthreads();
    float* sred = (float*)smb;            // [4][128] floats

    int q = lane & 3, g = lane >> 2;
    float bv[4][2], wv[4][2];
#pragma unroll
    for (int nt = 0; nt < 4; nt++)
#pragma unroll
        for (int c = 0; c < 2; c++) {
            int n = n0 + wn * 32 + nt * 8 + 2 * q + c;
            bv[nt][c] = b_attn[n];
            wv[nt][c] = w_ctx[n];
        }

#pragma unroll
    for (int mt = 0; mt < 4; mt++) {
        float s0 = 0.f, s1 = 0.f;
#pragma unroll
        for (int nt = 0; nt < 4; nt++)
#pragma unroll
            for (int c = 0; c < 2; c++) {
                s0 += tanh_fast(d[mt][nt][c]     + bv[nt][c]) * wv[nt][c];
                s1 += tanh_fast(d[mt][nt][2 + c] + bv[nt][c]) * wv[nt][c];
            }
        s0 += __shfl_xor_sync(0xffffffffu, s0, 1);
        s0 += __shfl_xor_sync(0xffffffffu, s0, 2);
        s1 += __shfl_xor_sync(0xffffffffu, s1, 1);
        s1 += __shfl_xor_sync(0xffffffffu, s1, 2);
        if (q == 0) {
            int ml = wm * 64 + mt * 16 + g;
            sred[wn * 128 + ml]     = s0;
            sred[wn * 128 + ml + 8] = s1;
        }
    }
    __syncthreads();

    if (tid < 128) {
        float v = sred[tid] + sred[128 + tid] + sred[256 + tid] + sred[384 + tid];
        g_part[bx * M_ + by * 128 + tid] = v;
    }
}

// ---------------------------------------------------------------------------
// Kernel 3a: softmax weights a[b,s] from 6 partial-logit slices
// ---------------------------------------------------------------------------
__global__ __launch_bounds__(256) void attn_weights_kernel() {
    int b = blockIdx.x, t = threadIdx.x;
    __shared__ float lg[S_];
    __shared__ float red[256];

    for (int s = t; s < S_; s += 256) {
        float v = 0.f;
#pragma unroll
        for (int nt = 0; nt < NT_; nt++) v += g_part[nt * M_ + b * S_ + s];
        lg[s] = v;
    }
    __syncthreads();

    float mx = fmaxf(lg[t], lg[t + 256]);
    red[t] = mx;
    __syncthreads();
    for (int o = 128; o > 0; o >>= 1) {
        if (t < o) red[t] = fmaxf(red[t], red[t + o]);
        __syncthreads();
    }
    mx = red[0];
    __syncthreads();

    float e0 = __expf(lg[t] - mx);
    float e1 = __expf(lg[t + 256] - mx);
    red[t] = e0 + e1;
    __syncthreads();
    for (int o = 128; o > 0; o >>= 1) {
        if (t < o) red[t] += red[t + o];
        __syncthreads();
    }
    float inv = 1.0f / red[0];

    g_attn[b * S_ + t]       = e0 * inv;
    g_attn[b * S_ + t + 256] = e1 * inv;
}

// ---------------------------------------------------------------------------
// Kernel 3b: partial weighted sums from fp16 Xh — grid (B, 3 hc, 16 sc),
// block 128, each thread 2 h via __half2 (128B/warp coalesced)
// ---------------------------------------------------------------------------
__global__ __launch_bounds__(128) void wsum_partial_kernel() {
    int b = blockIdx.x, hc = blockIdx.y, sc = blockIdx.z;
    int t = threadIdx.x;

    const __half2* Xp = (const __half2*)(Xh + (size_t)b * S_ * H_
                                         + (size_t)sc * 32 * H_ + hc * 256 + 2 * t);
    const float* ap = g_attn + b * S_ + sc * 32;

    float ax = 0.f, ay = 0.f;
#pragma unroll
    for (int s = 0; s < 32; s++) {
        float2 xf = __half22float2(Xp[(size_t)s * (H_ / 2)]);
        float a = ap[s];
        ax = fmaf(a, xf.x, ax);
        ay = fmaf(a, xf.y, ay);
    }
    float2* dst = (float2*)(g_sacc + (((b * 3) + hc) * 16 + sc) * 256 + 2 * t);
    *dst = make_float2(ax, ay);
}

// ---------------------------------------------------------------------------
// Kernel 3c: reduce 16 s-chunk partials -> sent_repr. grid (B, 3), block 256
// ---------------------------------------------------------------------------
__global__ __launch_bounds__(256) void wsum_reduce_kernel(float* __restrict__ sent) {
    int b = blockIdx.x, hc = blockIdx.y, t = threadIdx.x;
    const float* p = g_sacc + (((b * 3) + hc) * 16) * 256 + t;
    float acc = 0.f;
#pragma unroll
    for (int sc = 0; sc < 16; sc++) acc += p[sc * 256];
    sent[b * H_ + hc * 256 + t] = acc;
}

// ---------------------------------------------------------------------------
// launch
// ---------------------------------------------------------------------------
extern "C" void kernel_launch(void* const* d_in, const int* in_sizes, int n_in,
                              void* d_out, int out_size) {
    const float* X       = (const float*)d_in[0];
    const int* segments  = (const int*)d_in[1];
    const int* smask     = (const int*)d_in[2];
    const int* imask     = (const int*)d_in[3];
    const float* W       = (const float*)d_in[4];
    const float* b_attn  = (const float*)d_in[5];
    const float* w_ctx   = (const float*)d_in[6];

    float* out_vectors = (float*)d_out;
    float* sent        = (float*)d_out + (size_t)B_ * MS_ * H_;

    cudaFuncSetAttribute(gemm_mma_kernel,
                         cudaFuncAttributeMaxDynamicSharedMemorySize, SM_REQ);

    prep_kernel<<<SPLIT_BLOCKS, 256>>>(X, W);
    gemm_mma_kernel<<<GEMM_BLOCKS + B_ * MS_, 256, SM_REQ>>>(
        b_attn, w_ctx, X, segments, smask, imask, out_vectors);
    attn_weights_kernel<<<B_, 256>>>();
    wsum_partial_kernel<<<dim3(B_, 3, 16), 128>>>();
    wsum_reduce_kernel<<<dim3(B_, 3), 256>>>(sent);
}

// round 16
// speedup vs baseline: 1.1323x; 1.1323x over previous
#include <cuda_runtime.h>
#include <cuda_fp16.h>
#include <cstdint>

// Problem sizes (fixed by the dataset)
#define B_  32
#define S_  512
#define H_  768
#define MS_ 128
#define SL_ 8
#define M_  (B_ * S_)        // 16384 rows of X
#define NT_ 6                // partial-logit slices (one per n-block)

#define NEG_INF -1e30f

// Scratch (device globals: no allocation allowed)
__device__ float g_part[NT_ * M_];                 // partial logits per n-slice
__device__ float g_attn[M_];                       // softmax weights a[b,s]
__device__ float g_sacc[B_ * 3 * 16 * 256];        // weighted-sum partials
__device__ __half Xh[M_ * H_];                     // natural-layout fp16 X
// Fragment-major tiles: per (tile, chunk32) 2048 words (8KB), fp16.
__device__ uint4 Xfrag[M_ * H_ / 8];
__device__ uint4 Wfrag[H_ * H_ / 8];

// ---------------------------------------------------------------------------
// helpers
// ---------------------------------------------------------------------------
__device__ __forceinline__ uint32_t smem_u32(const void* p) {
    uint32_t a;
    asm("{ .reg .u64 t; cvta.to.shared.u64 t, %1; cvt.u32.u64 %0, t; }"
        : "=r"(a) : "l"(p));
    return a;
}

#define CP_ASYNC16(dst, src) \
    asm volatile("cp.async.cg.shared.global [%0], [%1], 16;" :: "r"(dst), "l"(src))
#define CP_COMMIT() asm volatile("cp.async.commit_group;" ::: "memory")
#define CP_WAIT0()  asm volatile("cp.async.wait_group 0;" ::: "memory")
#define CP_WAIT1()  asm volatile("cp.async.wait_group 1;" ::: "memory")

__device__ __forceinline__ void mma_f16(float* d, const uint32_t* a, const uint32_t* b) {
    asm volatile("mma.sync.aligned.m16n8k16.row.col.f32.f16.f16.f32 "
        "{%0,%1,%2,%3}, {%4,%5,%6,%7}, {%8,%9}, {%0,%1,%2,%3};"
        : "+f"(d[0]), "+f"(d[1]), "+f"(d[2]), "+f"(d[3])
        : "r"(a[0]), "r"(a[1]), "r"(a[2]), "r"(a[3]), "r"(b[0]), "r"(b[1]));
}

// fast tanh: tanh(x) = 1 - 2/(exp(2x)+1). 2 MUFU, abs err ~1e-6.
__device__ __forceinline__ float tanh_fast(float x) {
    float e = __expf(2.0f * x);
    return 1.0f - __fdividef(2.0f, e + 1.0f);
}

// pack two fp32 -> fp16x2 word
__device__ __forceinline__ uint32_t pack_h2(float x0, float x1) {
    __half h0 = __float2half_rn(x0);
    __half h1 = __float2half_rn(x1);
    return (uint32_t)__half_as_ushort(h0) | ((uint32_t)__half_as_ushort(h1) << 16);
}

// ---------------------------------------------------------------------------
// Fragment word layouts (word index within an 8KB chunk32 tile of 2048 words)
//   A tile: 128m x 32k.  W = ((mt*2+ks)*32 + lane)*4 + r
//   B tile: 128n x 32k, PAIRED: W = ((ntp*2+ks)*32 + lane)*4 + sub*2 + r
//     (ntp=nt>>1, sub=nt&1) — one LDS.128 feeds two adjacent n-tiles.
// ---------------------------------------------------------------------------

// Kernel 0: fused prepass + gather. 1D grid:
//   bid < 24*128         : X -> Xfrag + natural fp16 copy Xh
//   bid < 24*134         : W -> Wfrag (paired-B layout)
//   else                 : gather_max for segment bm = bid - 24*134
#define XSPLIT_BLOCKS (24 * 128)
#define SPLIT_BLOCKS  (24 * 134)
#define PREP_BLOCKS   (SPLIT_BLOCKS + B_ * MS_)

__global__ __launch_bounds__(256) void prep_kernel(
    const float* __restrict__ X, const float* __restrict__ W,
    const int* __restrict__ segments, const int* __restrict__ seg_mask,
    const int* __restrict__ idx_mask, float* __restrict__ out) {

    __shared__ float sbuf[4224];
    int bid = blockIdx.x;
    int t = threadIdx.x;

    if (bid < XSPLIT_BLOCKS) {
        int c = bid % 24, mb = bid / 24;
        float (*sX)[33] = (float (*)[33])sbuf;   // [128][33]
#pragma unroll
        for (int i = 0; i < 16; i++) {
            int idx = t + i * 256;  // 0..4095
            int m = idx >> 5, k = idx & 31;
            float x = X[(size_t)(mb * 128 + m) * H_ + c * 32 + k];
            sX[m][k] = x;
            Xh[(size_t)(mb * 128 + m) * H_ + c * 32 + k] = __float2half_rn(x);
        }
        __syncthreads();

        uint32_t* oh = (uint32_t*)Xfrag + ((size_t)mb * 24 + c) * 2048;
#pragma unroll
        for (int p = 0; p < 8; p++) {
            int w = t + p * 256;    // 0..2047
            int r = w & 3, lane = (w >> 2) & 31, g = w >> 7;   // g = mt*2+ks
            int mt = g >> 1, ks = g & 1;
            int m  = mt * 16 + ((r & 1) << 3) + (lane >> 2);
            int kp = ks * 8 + ((r >> 1) << 2) + (lane & 3);
            oh[w] = pack_h2(sX[m][2 * kp], sX[m][2 * kp + 1]);
        }
    } else if (bid < SPLIT_BLOCKS) {
        int bid2 = bid - XSPLIT_BLOCKS;
        int c = bid2 % 24, nb = bid2 / 24;
        float (*sW)[129] = (float (*)[129])sbuf; // [32][129]
#pragma unroll
        for (int i = 0; i < 16; i++) {
            int idx = t + i * 256;  // 0..4095
            int k = idx >> 7, n = idx & 127;
            sW[k][n] = W[(size_t)(c * 32 + k) * H_ + nb * 128 + n];
        }
        __syncthreads();

        uint32_t* oh = (uint32_t*)Wfrag + ((size_t)nb * 24 + c) * 2048;
#pragma unroll
        for (int p = 0; p < 8; p++) {
            int w = t + p * 256;
            int r2 = w & 3, lane = (w >> 2) & 31, g = w >> 7;  // g = ntp*2+ks
            int sub = r2 >> 1, r = r2 & 1;
            int ntp = g >> 1, ks = g & 1;
            int nt = ntp * 2 + sub;
            int n  = nt * 8 + (lane >> 2);
            int kp = ks * 8 + (r << 2) + (lane & 3);
            oh[w] = pack_h2(sW[2 * kp][n], sW[2 * kp + 1][n]);
        }
    } else {
        // gather_max: one segment per block, 192 active threads
        int bm = bid - SPLIT_BLOCKS;
        int b  = bm >> 7;
        int* sidx   = (int*)sbuf;
        int* svalid = (int*)sbuf + SL_;
        if (t < SL_) {
            sidx[t]   = segments[bm * SL_ + t];
            svalid[t] = idx_mask[bm * SL_ + t];
        }
        __syncthreads();
        if (t < 192) {
            const float4* Xb = (const float4*)(X + (size_t)b * S_ * H_);
            bool ok = seg_mask[bm] != 0;
            float4 r;
            if (!ok) {
                r = Xb[(size_t)(S_ - 2) * (H_ / 4) + t];
            } else {
                r = make_float4(NEG_INF, NEG_INF, NEG_INF, NEG_INF);
#pragma unroll
                for (int sl = 0; sl < SL_; sl++) {
                    if (svalid[sl]) {
                        float4 v = Xb[(size_t)sidx[sl] * (H_ / 4) + t];
                        r.x = fmaxf(r.x, v.x);
                        r.y = fmaxf(r.y, v.y);
                        r.z = fmaxf(r.z, v.z);
                        r.w = fmaxf(r.w, v.w);
                    }
                }
            }
            ((float4*)out)[(size_t)bm * (H_ / 4) + t] = r;
        }
    }
}

// ---------------------------------------------------------------------------
// Kernel 2: plain fp16 mma.sync GEMM + fused tanh/w_ctx epilogue
//   z = fp16(A) * fp16(W), fp32 accumulate, paired-B LDS.128 feeds
//   grid (6 n-blocks, 128 m-tiles), 256 threads (8 warps, warp tile 64x32)
//   BM=128 BN=128 BK=64, 12 iterations, 3-stage cp.async pipeline;
//   epilogue reduces across wn warps in SMEM -> one slice per CTA (NT=6).
// ---------------------------------------------------------------------------
#define SA_OFF 0
#define SB_OFF 16384
#define BUFSZ 32768
#define STAGES 3
#define SM_REQ (STAGES * BUFSZ)

__global__ __launch_bounds__(256, 2) void gemm_mma_kernel(
    const float* __restrict__ b_attn, const float* __restrict__ w_ctx) {

    extern __shared__ __align__(128) char smb[];
    uint32_t sbu = smem_u32(smb);

    int tid  = threadIdx.x;
    int wid  = tid >> 5, lane = tid & 31;
    int wm   = wid >> 2, wn = wid & 3;        // warp grid 2(m) x 4(n)
    int n0   = blockIdx.x * 128;

    const char* gA = (const char*)Xfrag + (size_t)blockIdx.y * 24 * 8192;
    const char* gB = (const char*)Wfrag + (size_t)blockIdx.x * 24 * 8192;

    float d[4][4][4];
#pragma unroll
    for (int i = 0; i < 4; i++)
#pragma unroll
        for (int j = 0; j < 4; j++)
#pragma unroll
            for (int r = 0; r < 4; r++) d[i][j][r] = 0.f;

    // staging: one chunk64 = two contiguous 8KB chunk32 images per operand
    auto stage = [&](int c, uint32_t buf) {   // c in chunk64 units (0..11)
        size_t tb = (size_t)c * 16384;
#pragma unroll
        for (int p = 0; p < 4; p++) {
            uint32_t off = (uint32_t)(tid + p * 256) * 16;
            CP_ASYNC16(buf + SA_OFF + off, gA + tb + off);
            CP_ASYNC16(buf + SB_OFF + off, gB + tb + off);
        }
    };

    auto compute = [&](const char* buf) {
#pragma unroll
        for (int half = 0; half < 2; half++) {
            const char* Ab = buf + SA_OFF + half * 8192;
            const char* Bb = buf + SB_OFF + half * 8192;
#pragma unroll
            for (int ks = 0; ks < 2; ks++) {
                uint32_t a[4][4], b[4][2];
#pragma unroll
                for (int mt = 0; mt < 4; mt++) {
                    uint32_t aoff = (((wm * 4 + mt) * 2 + ks) * 32 + lane) * 16;
                    uint4 v = *(const uint4*)(Ab + aoff);
                    a[mt][0] = v.x; a[mt][1] = v.y; a[mt][2] = v.z; a[mt][3] = v.w;
                }
                // paired B: one LDS.128 per ntp = two n-tiles
#pragma unroll
                for (int ntp = 0; ntp < 2; ntp++) {
                    uint32_t boff = (((wn * 2 + ntp) * 2 + ks) * 32 + lane) * 16;
                    uint4 v = *(const uint4*)(Bb + boff);
                    b[2 * ntp][0]     = v.x; b[2 * ntp][1]     = v.y;
                    b[2 * ntp + 1][0] = v.z; b[2 * ntp + 1][1] = v.w;
                }
#pragma unroll
                for (int mt = 0; mt < 4; mt++)
#pragma unroll
                    for (int nt = 0; nt < 4; nt++)
                        mma_f16(d[mt][nt], a[mt], b[nt]);
            }
        }
    };

    // ---- prologue: stages 0 and 1 in flight ----
    stage(0, sbu);
    CP_COMMIT();
    stage(1, sbu + BUFSZ);
    CP_COMMIT();

    // ---- mainloop: 12 chunk64s, 3-stage pipeline, compile-time stage idx ----
    for (int cb = 0; cb < 12; cb += 3) {
#pragma unroll
        for (int j = 0; j < 3; j++) {
            int c = cb + j;
            if (c == 11) CP_WAIT0(); else CP_WAIT1();   // oldest group (c) done
            __syncthreads();
            compute(smb + j * BUFSZ);
            if (c + 2 < 12) {
                stage(c + 2, sbu + ((j + 2) % 3) * BUFSZ);
                CP_COMMIT();
            }
        }
    }

    // ---- fused epilogue: tanh + dot(w_ctx), shfl + SMEM reduce -> 1 slice ----
    __syncthreads();                      // done reading stage SMEM
    float* sred = (float*)smb;            // [4][128] floats, 2KB

    int q = lane & 3, g = lane >> 2;
    float bv[4][2], wv[4][2];
#pragma unroll
    for (int nt = 0; nt < 4; nt++)
#pragma unroll
        for (int c = 0; c < 2; c++) {
            int n = n0 + wn * 32 + nt * 8 + 2 * q + c;
            bv[nt][c] = b_attn[n];
            wv[nt][c] = w_ctx[n];
        }

#pragma unroll
    for (int mt = 0; mt < 4; mt++) {
        float s0 = 0.f, s1 = 0.f;
#pragma unroll
        for (int nt = 0; nt < 4; nt++)
#pragma unroll
            for (int c = 0; c < 2; c++) {
                s0 += tanh_fast(d[mt][nt][c]     + bv[nt][c]) * wv[nt][c];
                s1 += tanh_fast(d[mt][nt][2 + c] + bv[nt][c]) * wv[nt][c];
            }
        s0 += __shfl_xor_sync(0xffffffffu, s0, 1);
        s0 += __shfl_xor_sync(0xffffffffu, s0, 2);
        s1 += __shfl_xor_sync(0xffffffffu, s1, 1);
        s1 += __shfl_xor_sync(0xffffffffu, s1, 2);
        if (q == 0) {
            int ml = wm * 64 + mt * 16 + g;
            sred[wn * 128 + ml]     = s0;
            sred[wn * 128 + ml + 8] = s1;
        }
    }
    __syncthreads();

    if (tid < 128) {
        float v = sred[tid] + sred[128 + tid] + sred[256 + tid] + sred[384 + tid];
        g_part[blockIdx.x * M_ + blockIdx.y * 128 + tid] = v;
    }
}

// ---------------------------------------------------------------------------
// Kernel 3a: softmax weights a[b,s] from 6 partial-logit slices
// ---------------------------------------------------------------------------
__global__ __launch_bounds__(256) void attn_weights_kernel() {
    int b = blockIdx.x, t = threadIdx.x;
    __shared__ float lg[S_];
    __shared__ float red[256];

    for (int s = t; s < S_; s += 256) {
        float v = 0.f;
#pragma unroll
        for (int nt = 0; nt < NT_; nt++) v += g_part[nt * M_ + b * S_ + s];
        lg[s] = v;
    }
    __syncthreads();

    float mx = fmaxf(lg[t], lg[t + 256]);
    red[t] = mx;
    __syncthreads();
    for (int o = 128; o > 0; o >>= 1) {
        if (t < o) red[t] = fmaxf(red[t], red[t + o]);
        __syncthreads();
    }
    mx = red[0];
    __syncthreads();

    float e0 = __expf(lg[t] - mx);
    float e1 = __expf(lg[t + 256] - mx);
    red[t] = e0 + e1;
    __syncthreads();
    for (int o = 128; o > 0; o >>= 1) {
        if (t < o) red[t] += red[t + o];
        __syncthreads();
    }
    float inv = 1.0f / red[0];

    g_attn[b * S_ + t]       = e0 * inv;
    g_attn[b * S_ + t + 256] = e1 * inv;
}

// ---------------------------------------------------------------------------
// Kernel 3b: partial weighted sums from fp16 Xh — grid (B, 3 hc, 16 sc),
// block 128, each thread 2 h via __half2 (128B/warp coalesced)
// ---------------------------------------------------------------------------
__global__ __launch_bounds__(128) void wsum_partial_kernel() {
    int b = blockIdx.x, hc = blockIdx.y, sc = blockIdx.z;
    int t = threadIdx.x;

    const __half2* Xp = (const __half2*)(Xh + (size_t)b * S_ * H_
                                         + (size_t)sc * 32 * H_ + hc * 256 + 2 * t);
    const float* ap = g_attn + b * S_ + sc * 32;

    float ax = 0.f, ay = 0.f;
#pragma unroll
    for (int s = 0; s < 32; s++) {
        float2 xf = __half22float2(Xp[(size_t)s * (H_ / 2)]);
        float a = ap[s];
        ax = fmaf(a, xf.x, ax);
        ay = fmaf(a, xf.y, ay);
    }
    float2* dst = (float2*)(g_sacc + (((b * 3) + hc) * 16 + sc) * 256 + 2 * t);
    *dst = make_float2(ax, ay);
}

// ---------------------------------------------------------------------------
// Kernel 3c: reduce 16 s-chunk partials -> sent_repr. grid (B, 3), block 256
// ---------------------------------------------------------------------------
__global__ __launch_bounds__(256) void wsum_reduce_kernel(float* __restrict__ sent) {
    int b = blockIdx.x, hc = blockIdx.y, t = threadIdx.x;
    const float* p = g_sacc + (((b * 3) + hc) * 16) * 256 + t;
    float acc = 0.f;
#pragma unroll
    for (int sc = 0; sc < 16; sc++) acc += p[sc * 256];
    sent[b * H_ + hc * 256 + t] = acc;
}

// ---------------------------------------------------------------------------
// launch
// ---------------------------------------------------------------------------
extern "C" void kernel_launch(void* const* d_in, const int* in_sizes, int n_in,
                              void* d_out, int out_size) {
    const float* X       = (const float*)d_in[0];
    const int* segments  = (const int*)d_in[1];
    const int* smask     = (const int*)d_in[2];
    const int* imask     = (const int*)d_in[3];
    const float* W       = (const float*)d_in[4];
    const float* b_attn  = (const float*)d_in[5];
    const float* w_ctx   = (const float*)d_in[6];

    float* out_vectors = (float*)d_out;
    float* sent        = (float*)d_out + (size_t)B_ * MS_ * H_;

    cudaFuncSetAttribute(gemm_mma_kernel,
                         cudaFuncAttributeMaxDynamicSharedMemorySize, SM_REQ);

    prep_kernel<<<PREP_BLOCKS, 256>>>(X, W, segments, smask, imask, out_vectors);
    gemm_mma_kernel<<<dim3(6, 128), 256, SM_REQ>>>(b_attn, w_ctx);
    attn_weights_kernel<<<B_, 256>>>();
    wsum_partial_kernel<<<dim3(B_, 3, 16), 128>>>();
    wsum_reduce_kernel<<<dim3(B_, 3), 256>>>(sent);
}